// round 16
// baseline (speedup 1.0000x reference)
#include <cuda_runtime.h>
#include <cstdint>

#define NBR    8
#define BATCH  128
#define HID    512
#define TT     256
#define G4     2048
#define THREADS 512

// ---------------- device scratch (static, no runtime alloc) ----------------
// h state fp16, B-fragment layout: g_ht[s][n][row][colp] (uint2),
// row = kc*16 + kb*4 + kk; uint2 = {f16x2(k=2kk,2kk+1 | b), f16x2(k=2kk+8,2kk+9 | b)},
// k relative to kb16 block; colp = b ^ (kk<<2). Ping-pong on step parity.
__device__ __align__(16) uint2 g_ht[2][NBR][128][128];
__device__ __align__(16) float g_ys[TT*NBR*BATCH];
__device__ __align__(16) float g_xt[TT*BATCH];          // x transposed: [t][b]
// producer flags: g_flag[(n*16+jt)*8] = number of completed writeouts (monotonic)
__device__ unsigned g_flag[NBR*16*8];
// read-completion counters: g_rd[(n*4+(t&3))*8], monotonic (16 per use)
__device__ unsigned g_rd[NBR*4*8];
// Whh fp16, A-fragment layout (gate-interleaved row permutation):
// per (n,jt): [kc 8][kb 4][mt 8][lane 32] uint4 = {a0,a1,a2,a3}
__device__ __align__(16) uint4 g_wimg[NBR][16][8192];

// ---------------- helpers ----------------
__device__ __forceinline__ float sigm(float x)  { return 1.0f / (1.0f + __expf(-x)); }
__device__ __forceinline__ float tanh_(float x) { return 2.0f / (1.0f + __expf(-2.0f * x)) - 1.0f; }

__device__ __forceinline__ uint32_t smem_u32(const void* p) {
    uint32_t a;
    asm("{ .reg .u64 t; cvta.to.shared.u64 t, %1; cvt.u32.u64 %0, t; }" : "=r"(a) : "l"(p));
    return a;
}
// pack two fp32 -> f16x2 {lo, hi}
__device__ __forceinline__ uint32_t packf16(float lo, float hi) {
    uint32_t r; asm("cvt.rn.f16x2.f32 %0, %1, %2;" : "=r"(r) : "f"(hi), "f"(lo)); return r;
}
__device__ __forceinline__ void cp16(uint32_t dst, const void* src) {
    asm volatile("cp.async.cg.shared.global [%0], [%1], 16;" :: "r"(dst), "l"(src) : "memory");
}
#define CP_COMMIT() asm volatile("cp.async.commit_group;" ::: "memory")
#define CP_WAIT(N)  asm volatile("cp.async.wait_group %0;" :: "n"(N) : "memory")

__device__ __forceinline__ void mma_f16(float* d, const uint32_t* a, const uint32_t* b) {
    asm volatile("mma.sync.aligned.m16n8k16.row.col.f32.f16.f16.f32 "
        "{%0,%1,%2,%3}, {%4,%5,%6,%7}, {%8,%9}, {%0,%1,%2,%3};"
        : "+f"(d[0]), "+f"(d[1]), "+f"(d[2]), "+f"(d[3])
        : "r"(a[0]), "r"(a[1]), "r"(a[2]), "r"(a[3]), "r"(b[0]), "r"(b[1]));
}

__device__ __forceinline__ unsigned ld_acq(const unsigned* p) {
    unsigned v;
    asm volatile("ld.acquire.gpu.global.u32 %0, [%1];" : "=r"(v) : "l"(p) : "memory");
    return v;
}
// wait for producers of B chunk kc (CTAs jt = 2kc, 2kc+1) to reach >= tgt writeouts
__device__ __forceinline__ void wait_pair(int n, int kc, unsigned tgt) {
    const unsigned* f0 = &g_flag[(n * 16 + 2 * kc) * 8];
    const unsigned* f1 = &g_flag[(n * 16 + 2 * kc + 1) * 8];
    while (ld_acq(f0) < tgt) { asm volatile("nanosleep.u32 64;"); }
    while (ld_acq(f1) < tgt) { asm volatile("nanosleep.u32 64;"); }
}

// ---------------- SMEM layout ----------------
// [0, 131072): W resident (8 chunks x 16 KB, A-fragment layout)
// [131072, 196608): B ring, 4 stages x 16 KB
#define OFF_BST 131072
#define BSTAGE  16384
#define OFF_X   196608        // 512 B
#define OFF_WB  197120        // float2[128] = 1 KB
#define OFF_H   198144        // float[32][132] = 16896 B
#define DSMEM_REQ 216064

// ---------------- prep: Whh -> fp16 A-fragments, permuted ----------------
__global__ void prep_w_kernel(const float* __restrict__ Whh) {
    unsigned i = blockIdx.x * blockDim.x + threadIdx.x;   // 2^20
    unsigned lane = i & 31, mt = (i >> 5) & 7, kb = (i >> 8) & 3;
    unsigned kc = (i >> 10) & 7, jt = (i >> 13) & 15, n = i >> 17;
    unsigned gid = lane >> 2, tig = lane & 3;
    unsigned g0 = gid >> 2, jl = gid & 3;
    unsigned j = jt * 32 + mt * 4 + jl;
    const float* rA = Whh + ((size_t)(n * G4 + g0 * HID + j)) * HID;        // gate g0
    const float* rB = Whh + ((size_t)(n * G4 + (g0 + 2) * HID + j)) * HID;  // gate g0+2
    unsigned k0 = kc * 64 + kb * 16 + 2 * tig;
    uint4 v;
    v.x = packf16(rA[k0],     rA[k0 + 1]);
    v.y = packf16(rB[k0],     rB[k0 + 1]);
    v.z = packf16(rA[k0 + 8], rA[k0 + 9]);
    v.w = packf16(rB[k0 + 8], rB[k0 + 9]);
    g_wimg[n][jt][kc * 1024 + (kb * 8 + mt) * 32 + lane] = v;
}

// ---------------- prep: h0 -> fp16 packed, sync state reset ----------------
__global__ void prep_h_kernel(const float* __restrict__ hn0) {
    unsigned i = blockIdx.x * blockDim.x + threadIdx.x;   // 131072
    unsigned b = i & 127, row = (i >> 7) & 127, n = i >> 14;
    unsigned kc = row >> 4, kb = (row >> 2) & 3, kk = row & 3;
    unsigned k0 = kc * 64 + kb * 16 + 2 * kk;
    const float* src = hn0 + ((size_t)(n * 128 + b)) * 512;
    uint2 v;
    v.x = packf16(src[k0],     src[k0 + 1]);
    v.y = packf16(src[k0 + 8], src[k0 + 9]);
    g_ht[0][n][row][b ^ (kk << 2)] = v;
    if (i < NBR * 16 * 8) g_flag[i] = 0;
    if (i < NBR * 4 * 8)  g_rd[i] = 0;
}

// ---------------- prep: transpose x ----------------
__global__ void prep_x_kernel(const float* __restrict__ cin) {
    unsigned i = blockIdx.x * blockDim.x + threadIdx.x;   // 32768
    unsigned b = i & 127, t = i >> 7;
    g_xt[t * BATCH + b] = cin[b * TT + t];
}

// ---------------- cp.async issue helper: one B chunk (1024 x 16B) ----------------
__device__ __forceinline__ void issue_B(uint32_t base, const uint2* srcB, int kc, int tid) {
    uint32_t dst = base + OFF_BST + (uint32_t)(kc & 3) * BSTAGE;
    const uint4* s = (const uint4*)(srcB + (size_t)kc * 2048);
    #pragma unroll
    for (int r = 0; r < 2; r++) {
        int i = r * THREADS + tid;
        cp16(dst + i * 16, s + i);
    }
    CP_COMMIT();
}

// ---------------- persistent kernel: all 256 LSTM steps ----------------
// grid 128 = n*16 + jt. 16 warps: wm = wid&3 (mt = wm*2..+1), wb = wid>>2 (32-col slice).
__global__ __launch_bounds__(THREADS, 1)
void steps_kernel(const float* __restrict__ Wih, const float* __restrict__ b_ih,
                  const float* __restrict__ b_hh)
{
    extern __shared__ __align__(16) unsigned char smem_raw[];
    uint32_t sb = smem_u32(smem_raw);
    uint32_t base = (sb + 1023) & ~1023u;
    unsigned char* bp = smem_raw + (base - sb);

    const int tid = threadIdx.x, wid = tid >> 5, lane = tid & 31;
    const int n = blockIdx.x >> 4, jt = blockIdx.x & 15;
    const int wm = wid & 3, wb = wid >> 2;
    const int q = lane >> 2, lr = lane & 3;      // q = gid, lr = tig/kk

    float*  smx  = (float*)(bp + OFF_X);
    float2* smwb = (float2*)(bp + OFF_WB);
    float*  smh  = (float*)(bp + OFF_H);

    if (tid < 128) {
        int gg = tid >> 5, jj = tid & 31;
        int row = n * G4 + gg * HID + jt * 32 + jj;
        smwb[tid] = make_float2(Wih[row], b_ih[row] + b_hh[row]);
    }
    __syncthreads();

    // per-thread gate constants (gates gA = q>>2 in {0,1} and gA+2)
    float2 wbA[2], wbB[2];
    {
        const int gA = q >> 2;
        #pragma unroll
        for (int m2 = 0; m2 < 2; m2++) {
            int jj = (wm * 2 + m2) * 4 + (q & 3);
            wbA[m2] = smwb[gA * 32 + jj];
            wbB[m2] = smwb[(gA + 2) * 32 + jj];
        }
    }

    // register-resident cell state (valid on lanes >= 16)
    float creg[2][4][2];
    #pragma unroll
    for (int a = 0; a < 2; a++)
        #pragma unroll
        for (int b2 = 0; b2 < 4; b2++) { creg[a][b2][0] = 0.0f; creg[a][b2][1] = 0.0f; }

    // ---- load W once: 8192 uint4 = 128 KB resident for all 256 steps ----
    {
        const uint4* srcW = &g_wimg[n][jt][0];
        #pragma unroll
        for (int r = 0; r < 16; r++) {
            int i = r * THREADS + tid;
            cp16(base + i * 16, srcW + i);
        }
        CP_COMMIT();
    }
    // prologue: B chunks 0..2 of step 0 (h0 from prep kernel, no flags needed)
    {
        const uint2* sB = &g_ht[0][n][0][0];
        issue_B(base, sB, 0, tid);
        issue_B(base, sB, 1, tid);
        issue_B(base, sB, 2, tid);
    }

    #pragma unroll 1
    for (int t = 0; t < TT; t++) {
        const int s = t & 1, dd = s ^ 1;
        const uint2* srcB = &g_ht[s][n][0][0];

        if (tid < 128) smx[tid] = g_xt[t * BATCH + tid];

        float acc[2][4][4];
        #pragma unroll
        for (int a0 = 0; a0 < 2; a0++)
            #pragma unroll
            for (int a1 = 0; a1 < 4; a1++)
                #pragma unroll
                for (int a2 = 0; a2 < 4; a2++) acc[a0][a1][a2] = 0.0f;

        #pragma unroll 1
        for (int kc = 0; kc < 8; kc++) {
            if (kc < 6)      CP_WAIT(2);
            else if (kc == 6) CP_WAIT(1);
            else              CP_WAIT(0);
            __syncthreads();

            if (kc == 7) {
                // all B reads of step t's input buffer have landed
                if (tid == 0) atomicAdd(&g_rd[(n * 4 + (t & 3)) * 8], 1u);
            }
            if (kc < 5) {
                wait_pair(n, kc + 3, (unsigned)t);
                issue_B(base, srcB, kc + 3, tid);
            }

            const uint32_t wbase = base + (uint32_t)kc * BSTAGE;            // W chunk kc
            const uint32_t bst   = base + OFF_BST + (uint32_t)(kc & 3) * BSTAGE;
            #pragma unroll
            for (int kb = 0; kb < 4; kb++) {
                uint32_t Af[2][4];
                #pragma unroll
                for (int m2 = 0; m2 < 2; m2++) {
                    uint32_t ad = wbase + (uint32_t)(((kb * 8 + (wm * 2 + m2)) * 32 + lane) * 16);
                    asm volatile("ld.shared.v4.b32 {%0,%1,%2,%3}, [%4];"
                        : "=r"(Af[m2][0]), "=r"(Af[m2][1]), "=r"(Af[m2][2]), "=r"(Af[m2][3])
                        : "r"(ad));
                }
                uint32_t Bf[4][2];
                #pragma unroll
                for (int nt = 0; nt < 4; nt++) {
                    int colp = (wb * 32 + nt * 8 + q) ^ (lr << 2);
                    uint32_t ad = bst + (uint32_t)(((kb * 4 + lr) * 128 + colp) * 8);
                    asm volatile("ld.shared.v2.b32 {%0,%1}, [%2];"
                        : "=r"(Bf[nt][0]), "=r"(Bf[nt][1]) : "r"(ad));
                }
                #pragma unroll
                for (int m2 = 0; m2 < 2; m2++)
                    #pragma unroll
                    for (int nt = 0; nt < 4; nt++)
                        mma_f16(acc[m2][nt], Af[m2], Bf[nt]);
            }
        }

        // ---- epilogue: gates in regs, shfl pair (i,g)<->(f,o), cell in regs ----
        #pragma unroll
        for (int m2 = 0; m2 < 2; m2++) {
            #pragma unroll
            for (int nt = 0; nt < 4; nt++) {
                int col = wb * 32 + nt * 8 + lr * 2;
                float hv[2];
                #pragma unroll
                for (int cp = 0; cp < 2; cp++) {
                    float xv = smx[col + cp];
                    float v0 = acc[m2][nt][cp]     + xv * wbA[m2].x + wbA[m2].y;
                    float v1 = acc[m2][nt][2 + cp] + xv * wbB[m2].x + wbB[m2].y;
                    float sv0 = sigm(v0);                      // sigm(i) | sigm(f)
                    float a1 = (lane < 16) ? (-2.0f * v1) : (-v1);
                    float e1 = __expf(a1);
                    float w1 = (lane < 16) ? (2.0f / (1.0f + e1) - 1.0f)   // tanh(g)
                                           : (1.0f / (1.0f + e1));          // sigm(o)
                    float pv = sv0 * w1;                        // lanes<16: sigm(i)*tanh(g)
                    float rcv = __shfl_xor_sync(0xffffffffu, pv, 16);
                    float cn = sv0 * creg[m2][nt][cp] + rcv;    // lanes>=16 valid
                    creg[m2][nt][cp] = cn;
                    hv[cp] = w1 * tanh_(cn);                    // lanes>=16: sigm(o)*tanh(cn)
                }
                if (lane >= 16) {
                    int jj = (wm * 2 + m2) * 4 + (q & 3);
                    *(float2*)&smh[jj * 132 + col] = make_float2(hv[0], hv[1]);
                }
            }
        }

        // WAR guard: all CTAs must have finished reading step t-1's input buffer
        // (same physical buffer we are about to overwrite).
        if (t >= 1 && tid == 0) {
            const unsigned* rc = &g_rd[(n * 4 + ((t - 1) & 3)) * 8];
            unsigned tg = 16u * ((unsigned)((t - 1) >> 2) + 1u);
            while (ld_acq(rc) < tg) { asm volatile("nanosleep.u32 64;"); }
        }
        __syncthreads();

        // ---- h writeout: fp16-pack into g_ht[dd] (B-fragment gmem layout) ----
        #pragma unroll
        for (int w2 = 0; w2 < 2; w2++) {
            int id = w2 * THREADS + tid;        // 0..1023
            int rowl = id >> 7;                 // 0..7
            int b  = id & 127;
            int kbl = rowl >> 2, kk = rowl & 3;
            int jb = kbl * 16 + 2 * kk;         // local j base
            float h0 = smh[jb * 132 + b];
            float h1 = smh[(jb + 1) * 132 + b];
            float h2 = smh[(jb + 8) * 132 + b];
            float h3 = smh[(jb + 9) * 132 + b];
            uint2 v;
            v.x = packf16(h0, h1);
            v.y = packf16(h2, h3);
            int rowg = (jt >> 1) * 16 + (2 * (jt & 1) + kbl) * 4 + kk;
            g_ht[dd][n][rowg][b ^ (kk << 2)] = v;
        }
        if (jt == 15 && tid < 128)
            g_ys[(size_t)t * NBR * BATCH + n * BATCH + tid] = smh[31 * 132 + tid];  // h[j=511]
        __syncthreads();

        // ---- publish own slice, then issue next step's B chunks 0..2 ----
        if (t < TT - 1) {
            if (tid == 0) {
                __threadfence();
                asm volatile("st.release.gpu.global.u32 [%0], %1;"
                    :: "l"(&g_flag[(n * 16 + jt) * 8]), "r"((unsigned)(t + 1)) : "memory");
            }
            const uint2* nB = &g_ht[dd][n][0][0];
            wait_pair(n, 0, (unsigned)(t + 1)); issue_B(base, nB, 0, tid);
            wait_pair(n, 1, (unsigned)(t + 1)); issue_B(base, nB, 1, tid);
            wait_pair(n, 2, (unsigned)(t + 1)); issue_B(base, nB, 2, tid);
        }
    }
    CP_WAIT(0);
    __syncthreads();
}

// ---------------- readout ----------------
__global__ void final_kernel(const float* __restrict__ x, const float* __restrict__ Wl,
                             const float* __restrict__ bl, float* __restrict__ out)
{
    __shared__ float red[TT];
    const int b = blockIdx.x;
    const int t = threadIdx.x;
    float r = 0.0f;
    #pragma unroll
    for (int nn = 0; nn < NBR; nn++)
        r += g_ys[(size_t)t * NBR * BATCH + nn * BATCH + b] * x[(nn * BATCH + b) * TT + t];
    for (int k = 0; k < NBR; k++) {
        red[t] = r * Wl[k * TT + t];
        __syncthreads();
        for (int sft = TT / 2; sft > 0; sft >>= 1) {
            if (t < sft) red[t] += red[t + sft];
            __syncthreads();
        }
        if (t == 0) out[b * NBR + k] = red[0] + bl[k];
        __syncthreads();
    }
}

// ---------------- launch ----------------
extern "C" void kernel_launch(void* const* d_in, const int* in_sizes, int n_in,
                              void* d_out, int out_size)
{
    (void)in_sizes; (void)n_in; (void)out_size;
    const float* x    = (const float*)d_in[0];
    const float* c    = (const float*)d_in[1];
    const float* Wih  = (const float*)d_in[2];
    const float* Whh  = (const float*)d_in[3];
    const float* b_ih = (const float*)d_in[4];
    const float* b_hh = (const float*)d_in[5];
    const float* hn0  = (const float*)d_in[6];
    const float* Wl   = (const float*)d_in[7];
    const float* bl   = (const float*)d_in[8];
    float* out = (float*)d_out;

    static bool attr_set = false;
    if (!attr_set) {
        cudaFuncSetAttribute(steps_kernel, cudaFuncAttributeMaxDynamicSharedMemorySize, DSMEM_REQ);
        attr_set = true;
    }

    prep_w_kernel<<<4096, 256>>>(Whh);
    prep_h_kernel<<<512, 256>>>(hn0);
    prep_x_kernel<<<128, 256>>>(c);
    steps_kernel<<<128, THREADS, DSMEM_REQ>>>(Wih, b_ih, b_hh);
    final_kernel<<<BATCH, TT>>>(x, Wl, bl, out);
}

// round 17
// speedup vs baseline: 1.0181x; 1.0181x over previous
#include <cuda_runtime.h>
#include <cstdint>

#define NBR    8
#define BATCH  128
#define HID    512
#define TT     256
#define G4     2048
#define THREADS 512

// ---------------- device scratch (static, no runtime alloc) ----------------
// h state fp16, B-fragment layout: g_ht[s][n][row][colp] (uint2),
// row = kc*16 + kb*4 + kk; uint2 = {f16x2(k=2kk,2kk+1 | b), f16x2(k=2kk+8,2kk+9 | b)},
// k relative to kb16 block; colp = b ^ (kk<<2). Ping-pong on step parity.
__device__ __align__(16) uint2 g_ht[2][NBR][128][128];
__device__ __align__(16) float g_ys[TT*NBR*BATCH];
__device__ __align__(16) float g_xt[TT*BATCH];          // x transposed: [t][b]
// producer flags: g_flag[(n*16+jt)*8] = number of completed writeouts (monotonic)
__device__ unsigned g_flag[NBR*16*8];
// Whh fp16, A-fragment layout (gate-interleaved row permutation):
// per (n,jt): [kc 8][kb 4][mt 8][lane 32] uint4 = {a0,a1,a2,a3}
__device__ __align__(16) uint4 g_wimg[NBR][16][8192];

// ---------------- helpers ----------------
__device__ __forceinline__ float sigm(float x)  { return 1.0f / (1.0f + __expf(-x)); }
__device__ __forceinline__ float tanh_(float x) { return 2.0f / (1.0f + __expf(-2.0f * x)) - 1.0f; }

__device__ __forceinline__ uint32_t smem_u32(const void* p) {
    uint32_t a;
    asm("{ .reg .u64 t; cvta.to.shared.u64 t, %1; cvt.u32.u64 %0, t; }" : "=r"(a) : "l"(p));
    return a;
}
// pack two fp32 -> f16x2 {lo, hi}
__device__ __forceinline__ uint32_t packf16(float lo, float hi) {
    uint32_t r; asm("cvt.rn.f16x2.f32 %0, %1, %2;" : "=r"(r) : "f"(hi), "f"(lo)); return r;
}
__device__ __forceinline__ void cp16(uint32_t dst, const void* src) {
    asm volatile("cp.async.cg.shared.global [%0], [%1], 16;" :: "r"(dst), "l"(src) : "memory");
}
#define CP_COMMIT() asm volatile("cp.async.commit_group;" ::: "memory")
#define CP_WAIT(N)  asm volatile("cp.async.wait_group %0;" :: "n"(N) : "memory")

__device__ __forceinline__ void mma_f16(float* d, const uint32_t* a, const uint32_t* b) {
    asm volatile("mma.sync.aligned.m16n8k16.row.col.f32.f16.f16.f32 "
        "{%0,%1,%2,%3}, {%4,%5,%6,%7}, {%8,%9}, {%0,%1,%2,%3};"
        : "+f"(d[0]), "+f"(d[1]), "+f"(d[2]), "+f"(d[3])
        : "r"(a[0]), "r"(a[1]), "r"(a[2]), "r"(a[3]), "r"(b[0]), "r"(b[1]));
}

__device__ __forceinline__ unsigned ld_acq(const unsigned* p) {
    unsigned v;
    asm volatile("ld.acquire.gpu.global.u32 %0, [%1];" : "=r"(v) : "l"(p) : "memory");
    return v;
}
// wait for producers of B chunk c (CTAs jt = 2c, 2c+1) to reach >= tgt writeouts.
// CALLED BY tid 0 ONLY.
__device__ __forceinline__ void wait_pair(int n, int c, unsigned tgt) {
    const unsigned* f0 = &g_flag[(n * 16 + 2 * c) * 8];
    const unsigned* f1 = &g_flag[(n * 16 + 2 * c + 1) * 8];
    while (ld_acq(f0) < tgt) { asm volatile("nanosleep.u32 32;"); }
    while (ld_acq(f1) < tgt) { asm volatile("nanosleep.u32 32;"); }
}

// ---------------- SMEM layout ----------------
// [0, 131072): W resident (8 chunks x 16 KB, A-fragment layout, by CHUNK index)
// [131072, 196608): B ring, 4 stages x 16 KB (by SLOT index & 3)
#define OFF_BST 131072
#define BSTAGE  16384
#define OFF_X   196608        // 512 B
#define OFF_WB  197120        // float2[128] = 1 KB
#define OFF_H   198144        // float[32][132] = 16896 B
#define DSMEM_REQ 216064

// ---------------- prep: Whh -> fp16 A-fragments, permuted ----------------
__global__ void prep_w_kernel(const float* __restrict__ Whh) {
    unsigned i = blockIdx.x * blockDim.x + threadIdx.x;   // 2^20
    unsigned lane = i & 31, mt = (i >> 5) & 7, kb = (i >> 8) & 3;
    unsigned kc = (i >> 10) & 7, jt = (i >> 13) & 15, n = i >> 17;
    unsigned gid = lane >> 2, tig = lane & 3;
    unsigned g0 = gid >> 2, jl = gid & 3;
    unsigned j = jt * 32 + mt * 4 + jl;
    const float* rA = Whh + ((size_t)(n * G4 + g0 * HID + j)) * HID;        // gate g0
    const float* rB = Whh + ((size_t)(n * G4 + (g0 + 2) * HID + j)) * HID;  // gate g0+2
    unsigned k0 = kc * 64 + kb * 16 + 2 * tig;
    uint4 v;
    v.x = packf16(rA[k0],     rA[k0 + 1]);
    v.y = packf16(rB[k0],     rB[k0 + 1]);
    v.z = packf16(rA[k0 + 8], rA[k0 + 9]);
    v.w = packf16(rB[k0 + 8], rB[k0 + 9]);
    g_wimg[n][jt][kc * 1024 + (kb * 8 + mt) * 32 + lane] = v;
}

// ---------------- prep: h0 -> fp16 packed, flag reset ----------------
__global__ void prep_h_kernel(const float* __restrict__ hn0) {
    unsigned i = blockIdx.x * blockDim.x + threadIdx.x;   // 131072
    unsigned b = i & 127, row = (i >> 7) & 127, n = i >> 14;
    unsigned kc = row >> 4, kb = (row >> 2) & 3, kk = row & 3;
    unsigned k0 = kc * 64 + kb * 16 + 2 * kk;
    const float* src = hn0 + ((size_t)(n * 128 + b)) * 512;
    uint2 v;
    v.x = packf16(src[k0],     src[k0 + 1]);
    v.y = packf16(src[k0 + 8], src[k0 + 9]);
    g_ht[0][n][row][b ^ (kk << 2)] = v;
    if (i < NBR * 16 * 8) g_flag[i] = 0;
}

// ---------------- prep: transpose x ----------------
__global__ void prep_x_kernel(const float* __restrict__ cin) {
    unsigned i = blockIdx.x * blockDim.x + threadIdx.x;   // 32768
    unsigned b = i & 127, t = i >> 7;
    g_xt[t * BATCH + b] = cin[b * TT + t];
}

// ---------------- cp.async issue helper: one B chunk (1024 x 16B) ----------------
// chunk = source chunk index (0..7), slot = ring slot (stage = slot & 3)
__device__ __forceinline__ void issue_B(uint32_t base, const uint2* srcB,
                                        int chunk, int slot, int tid) {
    uint32_t dst = base + OFF_BST + (uint32_t)(slot & 3) * BSTAGE;
    const uint4* s = (const uint4*)(srcB + (size_t)chunk * 2048);
    #pragma unroll
    for (int r = 0; r < 2; r++) {
        int i = r * THREADS + tid;
        cp16(dst + i * 16, s + i);
    }
    CP_COMMIT();
}

// ---------------- persistent kernel: all 256 LSTM steps ----------------
// grid 128 = n*16 + jt. 16 warps: wm = wid&3 (mt = wm*2..+1), wb = wid>>2 (32-col slice).
__global__ __launch_bounds__(THREADS, 1)
void steps_kernel(const float* __restrict__ Wih, const float* __restrict__ b_ih,
                  const float* __restrict__ b_hh)
{
    extern __shared__ __align__(16) unsigned char smem_raw[];
    uint32_t sb = smem_u32(smem_raw);
    uint32_t base = (sb + 1023) & ~1023u;
    unsigned char* bp = smem_raw + (base - sb);

    const int tid = threadIdx.x, wid = tid >> 5, lane = tid & 31;
    const int n = blockIdx.x >> 4, jt = blockIdx.x & 15;
    const int wm = wid & 3, wb = wid >> 2;
    const int q = lane >> 2, lr = lane & 3;      // q = gid, lr = tig/kk
    const int base0 = jt >> 1;                   // own chunk first

    float*  smx  = (float*)(bp + OFF_X);
    float2* smwb = (float2*)(bp + OFF_WB);
    float*  smh  = (float*)(bp + OFF_H);

    if (tid < 128) {
        int gg = tid >> 5, jj = tid & 31;
        int row = n * G4 + gg * HID + jt * 32 + jj;
        smwb[tid] = make_float2(Wih[row], b_ih[row] + b_hh[row]);
    }
    __syncthreads();

    // per-thread gate constants (gates gA = q>>2 in {0,1} and gA+2)
    float2 wbA[2], wbB[2];
    {
        const int gA = q >> 2;
        #pragma unroll
        for (int m2 = 0; m2 < 2; m2++) {
            int jj = (wm * 2 + m2) * 4 + (q & 3);
            wbA[m2] = smwb[gA * 32 + jj];
            wbB[m2] = smwb[(gA + 2) * 32 + jj];
        }
    }

    // register-resident cell state (valid on lanes >= 16)
    float creg[2][4][2];
    #pragma unroll
    for (int a = 0; a < 2; a++)
        #pragma unroll
        for (int b2 = 0; b2 < 4; b2++) { creg[a][b2][0] = 0.0f; creg[a][b2][1] = 0.0f; }

    // ---- load W once: 8192 uint4 = 128 KB resident for all 256 steps ----
    {
        const uint4* srcW = &g_wimg[n][jt][0];
        #pragma unroll
        for (int r = 0; r < 16; r++) {
            int i = r * THREADS + tid;
            cp16(base + i * 16, srcW + i);
        }
        CP_COMMIT();
    }
    // prologue: B slots 0..2 of step 0 (h0 from prep kernel, no flags needed)
    {
        const uint2* sB = &g_ht[0][n][0][0];
        issue_B(base, sB, (base0 + 0) & 7, 0, tid);
        issue_B(base, sB, (base0 + 1) & 7, 1, tid);
        issue_B(base, sB, (base0 + 2) & 7, 2, tid);
    }

    #pragma unroll 1
    for (int t = 0; t < TT; t++) {
        const int s = t & 1, dd = s ^ 1;
        const uint2* srcB = &g_ht[s][n][0][0];

        if (tid < 128) smx[tid] = g_xt[t * BATCH + tid];

        float acc[2][4][4];
        #pragma unroll
        for (int a0 = 0; a0 < 2; a0++)
            #pragma unroll
            for (int a1 = 0; a1 < 4; a1++)
                #pragma unroll
                for (int a2 = 0; a2 < 4; a2++) acc[a0][a1][a2] = 0.0f;

        #pragma unroll 1
        for (int i = 0; i < 8; i++) {
            if (i < 6)       CP_WAIT(2);
            else if (i == 6) CP_WAIT(1);
            else             CP_WAIT(0);
            // tid0 confirms producers of the chunk we are about to issue
            if (tid == 0 && i < 5 && t > 0)
                wait_pair(n, (base0 + i + 3) & 7, (unsigned)t);
            __syncthreads();

            if (i < 5) issue_B(base, srcB, (base0 + i + 3) & 7, i + 3, tid);

            const int ci = (base0 + i) & 7;
            const uint32_t wbase = base + (uint32_t)ci * BSTAGE;            // W chunk ci
            const uint32_t bst   = base + OFF_BST + (uint32_t)(i & 3) * BSTAGE;
            #pragma unroll
            for (int kb = 0; kb < 4; kb++) {
                uint32_t Af[2][4];
                #pragma unroll
                for (int m2 = 0; m2 < 2; m2++) {
                    uint32_t ad = wbase + (uint32_t)(((kb * 8 + (wm * 2 + m2)) * 32 + lane) * 16);
                    asm volatile("ld.shared.v4.b32 {%0,%1,%2,%3}, [%4];"
                        : "=r"(Af[m2][0]), "=r"(Af[m2][1]), "=r"(Af[m2][2]), "=r"(Af[m2][3])
                        : "r"(ad));
                }
                uint32_t Bf[4][2];
                #pragma unroll
                for (int nt = 0; nt < 4; nt++) {
                    int colp = (wb * 32 + nt * 8 + q) ^ (lr << 2);
                    uint32_t ad = bst + (uint32_t)(((kb * 4 + lr) * 128 + colp) * 8);
                    asm volatile("ld.shared.v2.b32 {%0,%1}, [%2];"
                        : "=r"(Bf[nt][0]), "=r"(Bf[nt][1]) : "r"(ad));
                }
                #pragma unroll
                for (int m2 = 0; m2 < 2; m2++)
                    #pragma unroll
                    for (int nt = 0; nt < 4; nt++)
                        mma_f16(acc[m2][nt], Af[m2], Bf[nt]);
            }
        }

        // ---- epilogue: gates in regs, shfl pair (i,g)<->(f,o), cell in regs ----
        #pragma unroll
        for (int m2 = 0; m2 < 2; m2++) {
            #pragma unroll
            for (int nt = 0; nt < 4; nt++) {
                int col = wb * 32 + nt * 8 + lr * 2;
                float hv[2];
                #pragma unroll
                for (int cp = 0; cp < 2; cp++) {
                    float xv = smx[col + cp];
                    float v0 = acc[m2][nt][cp]     + xv * wbA[m2].x + wbA[m2].y;
                    float v1 = acc[m2][nt][2 + cp] + xv * wbB[m2].x + wbB[m2].y;
                    float sv0 = sigm(v0);                      // sigm(i) | sigm(f)
                    float a1 = (lane < 16) ? (-2.0f * v1) : (-v1);
                    float e1 = __expf(a1);
                    float w1 = (lane < 16) ? (2.0f / (1.0f + e1) - 1.0f)   // tanh(g)
                                           : (1.0f / (1.0f + e1));          // sigm(o)
                    float pv = sv0 * w1;                        // lanes<16: sigm(i)*tanh(g)
                    float rcv = __shfl_xor_sync(0xffffffffu, pv, 16);
                    float cn = sv0 * creg[m2][nt][cp] + rcv;    // lanes>=16 valid
                    creg[m2][nt][cp] = cn;
                    hv[cp] = w1 * tanh_(cn);                    // lanes>=16: sigm(o)*tanh(cn)
                }
                if (lane >= 16) {
                    int jj = (wm * 2 + m2) * 4 + (q & 3);
                    *(float2*)&smh[jj * 132 + col] = make_float2(hv[0], hv[1]);
                }
            }
        }
        __syncthreads();

        // ---- h writeout: fp16-pack into g_ht[dd] (B-fragment gmem layout) ----
        #pragma unroll
        for (int w2 = 0; w2 < 2; w2++) {
            int id = w2 * THREADS + tid;        // 0..1023
            int rowl = id >> 7;                 // 0..7
            int b  = id & 127;
            int kbl = rowl >> 2, kk = rowl & 3;
            int jb = kbl * 16 + 2 * kk;         // local j base
            float h0 = smh[jb * 132 + b];
            float h1 = smh[(jb + 1) * 132 + b];
            float h2 = smh[(jb + 8) * 132 + b];
            float h3 = smh[(jb + 9) * 132 + b];
            uint2 v;
            v.x = packf16(h0, h1);
            v.y = packf16(h2, h3);
            int rowg = (jt >> 1) * 16 + (2 * (jt & 1) + kbl) * 4 + kk;
            g_ht[dd][n][rowg][b ^ (kk << 2)] = v;
        }
        if (jt == 15 && tid < 128)
            g_ys[(size_t)t * NBR * BATCH + n * BATCH + tid] = smh[31 * 132 + tid];  // h[j=511]
        __syncthreads();

        // ---- publish own slice, confirm first 3 producers, refill slots 0..2 ----
        if (t < TT - 1) {
            if (tid == 0) {
                __threadfence();
                asm volatile("st.release.gpu.global.u32 [%0], %1;"
                    :: "l"(&g_flag[(n * 16 + jt) * 8]), "r"((unsigned)(t + 1)) : "memory");
                wait_pair(n, (base0 + 0) & 7, (unsigned)(t + 1));
                wait_pair(n, (base0 + 1) & 7, (unsigned)(t + 1));
                wait_pair(n, (base0 + 2) & 7, (unsigned)(t + 1));
            }
            __syncthreads();
            const uint2* nB = &g_ht[dd][n][0][0];
            issue_B(base, nB, (base0 + 0) & 7, 0, tid);
            issue_B(base, nB, (base0 + 1) & 7, 1, tid);
            issue_B(base, nB, (base0 + 2) & 7, 2, tid);
        }
    }
    CP_WAIT(0);
    __syncthreads();
}

// ---------------- readout ----------------
__global__ void final_kernel(const float* __restrict__ x, const float* __restrict__ Wl,
                             const float* __restrict__ bl, float* __restrict__ out)
{
    __shared__ float red[TT];
    const int b = blockIdx.x;
    const int t = threadIdx.x;
    float r = 0.0f;
    #pragma unroll
    for (int nn = 0; nn < NBR; nn++)
        r += g_ys[(size_t)t * NBR * BATCH + nn * BATCH + b] * x[(nn * BATCH + b) * TT + t];
    for (int k = 0; k < NBR; k++) {
        red[t] = r * Wl[k * TT + t];
        __syncthreads();
        for (int sft = TT / 2; sft > 0; sft >>= 1) {
            if (t < sft) red[t] += red[t + sft];
            __syncthreads();
        }
        if (t == 0) out[b * NBR + k] = red[0] + bl[k];
        __syncthreads();
    }
}

// ---------------- launch ----------------
extern "C" void kernel_launch(void* const* d_in, const int* in_sizes, int n_in,
                              void* d_out, int out_size)
{
    (void)in_sizes; (void)n_in; (void)out_size;
    const float* x    = (const float*)d_in[0];
    const float* c    = (const float*)d_in[1];
    const float* Wih  = (const float*)d_in[2];
    const float* Whh  = (const float*)d_in[3];
    const float* b_ih = (const float*)d_in[4];
    const float* b_hh = (const float*)d_in[5];
    const float* hn0  = (const float*)d_in[6];
    const float* Wl   = (const float*)d_in[7];
    const float* bl   = (const float*)d_in[8];
    float* out = (float*)d_out;

    static bool attr_set = false;
    if (!attr_set) {
        cudaFuncSetAttribute(steps_kernel, cudaFuncAttributeMaxDynamicSharedMemorySize, DSMEM_REQ);
        attr_set = true;
    }

    prep_w_kernel<<<4096, 256>>>(Whh);
    prep_h_kernel<<<512, 256>>>(hn0);
    prep_x_kernel<<<128, 256>>>(c);
    steps_kernel<<<128, THREADS, DSMEM_REQ>>>(Wih, b_ih, b_hh);
    final_kernel<<<BATCH, TT>>>(x, Wl, bl, out);
}